// round 2
// baseline (speedup 1.0000x reference)
#include <cuda_runtime.h>
#include <cuda_fp16.h>
#include <cstdint>

// ---------------------------------------------------------------------------
// Problem constants
// ---------------------------------------------------------------------------
#define M_TOTAL 4096            // 4 * 1024
#define N_TOTAL 11008
#define K_TOTAL 4096
#define PACKED_LEN (N_TOTAL * K_TOTAL / 4)   // int32 elements, one byte each

#define BM 128
#define BN 128
#define BK 64                   // fp16 elems per stage = 128 bytes = SW128 atom row
#define S_STAGES (K_TOTAL / BK) // 64
#define NTHREADS 256

// SMEM: 3 stage buffers, each A tile 16KB + B tile 16KB
#define A_TILE_BYTES 16384
#define B_TILE_BYTES 16384
#define STAGE_BYTES  (A_TILE_BYTES + B_TILE_BYTES)     // 32768
#define SMEM_TOTAL_BYTES (3 * STAGE_BYTES)             // 98304

// ---------------------------------------------------------------------------
// Device scratch (module-static; no runtime allocation)
// ---------------------------------------------------------------------------
__device__ __half g_A[(size_t)M_TOTAL * K_TOTAL];   // 32 MB, x in fp16
__device__ __half g_B[(size_t)N_TOTAL * K_TOTAL];   // 88 MB, dequantized W

// ---------------------------------------------------------------------------
// PTX helpers (baseline ISA only: cp.async sm_80, ldmatrix sm_75, mma sm_80)
// ---------------------------------------------------------------------------
static __device__ __forceinline__ uint32_t smem_u32(const void* p) {
    uint32_t a;
    asm("{ .reg .u64 t; cvta.to.shared.u64 t, %1; cvt.u32.u64 %0, t; }"
        : "=r"(a) : "l"(p));
    return a;
}

#define CP_ASYNC16(dst, src) \
    asm volatile("cp.async.cg.shared.global [%0], [%1], 16;" \
                 :: "r"(dst), "l"(__cvta_generic_to_global(src)) : "memory")
#define CP_COMMIT() asm volatile("cp.async.commit_group;" ::: "memory")
#define CP_WAIT1()  asm volatile("cp.async.wait_group 1;" ::: "memory")
#define CP_WAIT0()  asm volatile("cp.async.wait_group 0;" ::: "memory")

#define LDMATRIX_X4(r0, r1, r2, r3, addr) \
    asm volatile("ldmatrix.sync.aligned.m8n8.x4.shared.b16 {%0,%1,%2,%3}, [%4];" \
                 : "=r"(r0), "=r"(r1), "=r"(r2), "=r"(r3) : "r"(addr))

// D = A*B + D, m16n8k16, f16 in, f32 acc
#define MMA_16816(c0, c1, c2, c3, a0, a1, a2, a3, b0, b1) \
    asm volatile("mma.sync.aligned.m16n8k16.row.col.f32.f16.f16.f32 " \
                 "{%0,%1,%2,%3}, {%4,%5,%6,%7}, {%8,%9}, {%0,%1,%2,%3};" \
                 : "+f"(c0), "+f"(c1), "+f"(c2), "+f"(c3) \
                 : "r"(a0), "r"(a1), "r"(a2), "r"(a3), "r"(b0), "r"(b1))

// SW128 swizzle of a byte offset within a [row][128B] tile:
// off = row*128 + cb (cb < 128)  ->  row*128 + (cb ^ ((row & 7) << 4))
#define SW128(off) ((off) ^ (((off) >> 3) & 0x70))

// ---------------------------------------------------------------------------
// Prologue 1: x f32 -> fp16
// ---------------------------------------------------------------------------
__global__ void __launch_bounds__(256) convert_x_kernel(const float4* __restrict__ x) {
    int i = blockIdx.x * 256 + threadIdx.x;     // grid sized exactly
    float4 v = x[i];
    __half2* A2 = reinterpret_cast<__half2*>(g_A);
    A2[2 * i]     = __floats2half2_rn(v.x, v.y);
    A2[2 * i + 1] = __floats2half2_rn(v.z, v.w);
}

// ---------------------------------------------------------------------------
// Prologue 2: dequantize packed weights -> fp16 [N, K]
// q = ((byte >> 2j) & 3) - 1  ->  {-1, 0, 1, 2}, all exact in fp16
// ---------------------------------------------------------------------------
static __device__ __forceinline__ uint2 dequant4(unsigned v) {
    // fp16 patterns for field-1: 0 -> -1 (0xBC00), 1 -> 0, 2 -> 1 (0x3C00), 3 -> 2 (0x4000)
    const unsigned long long LUT = 0x40003C000000BC00ull;
    unsigned h0 = (unsigned)((LUT >> (16u * (v & 3u))) & 0xFFFFu);
    unsigned h1 = (unsigned)((LUT >> (16u * ((v >> 2) & 3u))) & 0xFFFFu);
    unsigned h2 = (unsigned)((LUT >> (16u * ((v >> 4) & 3u))) & 0xFFFFu);
    unsigned h3 = (unsigned)((LUT >> (16u * ((v >> 6) & 3u))) & 0xFFFFu);
    return make_uint2(h0 | (h1 << 16), h2 | (h3 << 16));
}

__global__ void __launch_bounds__(256) dequant_w_kernel(const int4* __restrict__ pw) {
    int i = blockIdx.x * 256 + threadIdx.x;     // grid sized exactly
    int4 p = pw[i];
    uint2* B2 = reinterpret_cast<uint2*>(g_B);  // 4 halves per uint2
    B2[4 * i + 0] = dequant4((unsigned)p.x);
    B2[4 * i + 1] = dequant4((unsigned)p.y);
    B2[4 * i + 2] = dequant4((unsigned)p.z);
    B2[4 * i + 3] = dequant4((unsigned)p.w);
}

// ---------------------------------------------------------------------------
// Stage loader: 128x64 fp16 A tile + 128x64 fp16 B tile, SW128-swizzled rows
// ---------------------------------------------------------------------------
static __device__ __forceinline__ void load_stage(
    int s, int tid, uint32_t smem_base,
    const __half* __restrict__ Abase, const __half* __restrict__ Bbase)
{
    uint32_t aB = smem_base + (uint32_t)(s % 3) * STAGE_BYTES;
    uint32_t bB = aB + A_TILE_BYTES;
    const __half* As = Abase + (size_t)s * BK;
    const __half* Bs = Bbase + (size_t)s * BK;
    #pragma unroll
    for (int c = 0; c < 4; c++) {
        int chunk = tid + c * NTHREADS;   // 0..1023
        int row = chunk >> 3;             // 0..127
        int col = chunk & 7;              // 16B chunk within 128B row
        uint32_t sw = SW128((uint32_t)(row * 128 + col * 16));
        CP_ASYNC16(aB + sw, As + (size_t)row * K_TOTAL + col * 8);
        CP_ASYNC16(bB + sw, Bs + (size_t)row * K_TOTAL + col * 8);
    }
    CP_COMMIT();
}

// ---------------------------------------------------------------------------
// Main GEMM: 128x128 CTA tile, 8 warps (2 M x 4 N), warp tile 64x32,
// 3-stage cp.async pipeline, mma.sync.m16n8k16 (HMMA fallback path)
// ---------------------------------------------------------------------------
__global__ void __launch_bounds__(NTHREADS, 2)
gemm_kernel(const float* __restrict__ scale_p, float* __restrict__ out)
{
    extern __shared__ char smem[];
    uint32_t smem_base = smem_u32(smem);
    int tid = threadIdx.x;
    int wid = tid >> 5;
    int lid = tid & 31;

    int nBase = blockIdx.x * BN;
    int mBase = blockIdx.y * BM;

    int warp_m = (wid & 1) * 64;   // 0 or 64 within CTA tile
    int warp_n = (wid >> 1) * 32;  // 0,32,64,96

    const __half* Abase = g_A + (size_t)mBase * K_TOTAL;
    const __half* Bbase = g_B + (size_t)nBase * K_TOTAL;

    // Per-lane ldmatrix addressing pieces (identical scheme for A and B,
    // both stored [row][K] with row-major 128B swizzled rows):
    //   mat = lid>>3 (quadrant), r = lid&7 (row within 8)
    //   row = base + (mat&1)*8 + r ; colbyte = kstep*32 + (mat>>1)*16
    //   smem addr = tile + row*128 + (colbyte ^ (r<<4))
    int mat  = lid >> 3;
    int r    = lid & 7;
    int rowA0 = warp_m + ((mat & 1) << 3) + r;   // + mi*16
    int rowB0 = warp_n + ((mat & 1) << 3) + r;   // + nb*16
    uint32_t cxor = (uint32_t)(((mat >> 1) << 4)) ^ ((uint32_t)r << 4);

    float acc[4][4][4];   // [mi][ni][4]
    #pragma unroll
    for (int mi = 0; mi < 4; mi++)
        #pragma unroll
        for (int ni = 0; ni < 4; ni++)
            #pragma unroll
            for (int c = 0; c < 4; c++) acc[mi][ni][c] = 0.0f;

    load_stage(0, tid, smem_base, Abase, Bbase);
    load_stage(1, tid, smem_base, Abase, Bbase);

    for (int s = 0; s < S_STAGES; s++) {
        if (s + 1 < S_STAGES) { CP_WAIT1(); } else { CP_WAIT0(); }
        __syncthreads();

        if (s + 2 < S_STAGES) load_stage(s + 2, tid, smem_base, Abase, Bbase);

        uint32_t aT = smem_base + (uint32_t)(s % 3) * STAGE_BYTES;
        uint32_t bT = aT + A_TILE_BYTES;

        #pragma unroll
        for (int ks = 0; ks < 4; ks++) {
            uint32_t kb = (uint32_t)(ks * 32) ^ cxor;   // swizzled column byte

            uint32_t a[4][4];
            #pragma unroll
            for (int mi = 0; mi < 4; mi++) {
                uint32_t addr = aT + (uint32_t)((rowA0 + mi * 16) * 128) + kb;
                LDMATRIX_X4(a[mi][0], a[mi][1], a[mi][2], a[mi][3], addr);
            }
            uint32_t b[4][2];
            #pragma unroll
            for (int nb = 0; nb < 2; nb++) {
                uint32_t r0, r1, r2, r3;
                uint32_t addr = bT + (uint32_t)((rowB0 + nb * 16) * 128) + kb;
                LDMATRIX_X4(r0, r1, r2, r3, addr);
                b[nb * 2 + 0][0] = r0; b[nb * 2 + 0][1] = r2;
                b[nb * 2 + 1][0] = r1; b[nb * 2 + 1][1] = r3;
            }

            #pragma unroll
            for (int mi = 0; mi < 4; mi++)
                #pragma unroll
                for (int ni = 0; ni < 4; ni++)
                    MMA_16816(acc[mi][ni][0], acc[mi][ni][1],
                              acc[mi][ni][2], acc[mi][ni][3],
                              a[mi][0], a[mi][1], a[mi][2], a[mi][3],
                              b[ni][0], b[ni][1]);
        }
    }

    // Epilogue: c frag m16n8 f32 layout: lane l -> row = l/4 (+8), col = (l%4)*2
    float scale = *scale_p;
    int erow = lid >> 2;
    int ecol = (lid & 3) * 2;

    #pragma unroll
    for (int mi = 0; mi < 4; mi++) {
        #pragma unroll
        for (int ni = 0; ni < 4; ni++) {
            int row = mBase + warp_m + mi * 16 + erow;
            int col = nBase + warp_n + ni * 8 + ecol;
            float2 v0 = make_float2(acc[mi][ni][0] * scale, acc[mi][ni][1] * scale);
            float2 v1 = make_float2(acc[mi][ni][2] * scale, acc[mi][ni][3] * scale);
            *reinterpret_cast<float2*>(out + (size_t)row * N_TOTAL + col) = v0;
            *reinterpret_cast<float2*>(out + (size_t)(row + 8) * N_TOTAL + col) = v1;
        }
    }
}

// ---------------------------------------------------------------------------
// Harness entry
// ---------------------------------------------------------------------------
extern "C" void kernel_launch(void* const* d_in, const int* in_sizes, int n_in,
                              void* d_out, int out_size)
{
    const float* x  = (const float*)d_in[0];
    const int*   pw = (const int*)d_in[1];
    const float* ws = (const float*)d_in[2];
    float* out = (float*)d_out;

    cudaFuncSetAttribute(gemm_kernel,
                         cudaFuncAttributeMaxDynamicSharedMemorySize,
                         SMEM_TOTAL_BYTES);

    convert_x_kernel<<<(M_TOTAL * K_TOTAL / 4) / 256, 256>>>(
        reinterpret_cast<const float4*>(x));
    dequant_w_kernel<<<(PACKED_LEN / 4) / 256, 256>>>(
        reinterpret_cast<const int4*>(pw));
    gemm_kernel<<<dim3(N_TOTAL / BN, M_TOTAL / BM), NTHREADS, SMEM_TOTAL_BYTES>>>(ws, out);
}

// round 3
// speedup vs baseline: 1.0062x; 1.0062x over previous
#include <cuda_runtime.h>
#include <cuda_fp16.h>
#include <cstdint>

// ---------------------------------------------------------------------------
// Problem constants
// ---------------------------------------------------------------------------
#define M_TOTAL 4096            // 4 * 1024
#define N_TOTAL 11008
#define K_TOTAL 4096
#define PACKED_LEN (N_TOTAL * K_TOTAL / 4)   // int32 elements, one byte each

#define BM 128
#define BN 128
#define BK 64                   // fp16 elems per stage = 128 bytes = SW128 atom row
#define S_STAGES (K_TOTAL / BK) // 64
#define NTHREADS 256

// SMEM: 3 stage buffers, each A tile 16KB + B tile 16KB
#define A_TILE_BYTES 16384
#define B_TILE_BYTES 16384
#define STAGE_BYTES  (A_TILE_BYTES + B_TILE_BYTES)     // 32768
#define SMEM_TOTAL_BYTES (3 * STAGE_BYTES)             // 98304

// Prep kernel grid split
#define CONV_BLOCKS ((M_TOTAL * K_TOTAL / 4) / 256)    // 16384
#define DEQ_BLOCKS  ((PACKED_LEN / 4) / 256)           // 11008
#define PREP_BLOCKS (CONV_BLOCKS + DEQ_BLOCKS)

// ---------------------------------------------------------------------------
// Device scratch (module-static; no runtime allocation)
// ---------------------------------------------------------------------------
__device__ __half g_A[(size_t)M_TOTAL * K_TOTAL];   // 32 MB, x in fp16
__device__ __half g_B[(size_t)N_TOTAL * K_TOTAL];   // 88 MB, dequantized W

// ---------------------------------------------------------------------------
// PTX helpers (baseline ISA only: cp.async sm_80, ldmatrix sm_75, mma sm_80)
// ---------------------------------------------------------------------------
static __device__ __forceinline__ uint32_t smem_u32(const void* p) {
    uint32_t a;
    asm("{ .reg .u64 t; cvta.to.shared.u64 t, %1; cvt.u32.u64 %0, t; }"
        : "=r"(a) : "l"(p));
    return a;
}

#define CP_ASYNC16(dst, src) \
    asm volatile("cp.async.cg.shared.global [%0], [%1], 16;" \
                 :: "r"(dst), "l"(__cvta_generic_to_global(src)) : "memory")
#define CP_COMMIT() asm volatile("cp.async.commit_group;" ::: "memory")
#define CP_WAIT1()  asm volatile("cp.async.wait_group 1;" ::: "memory")
#define CP_WAIT0()  asm volatile("cp.async.wait_group 0;" ::: "memory")

#define LDMATRIX_X4(r0, r1, r2, r3, addr) \
    asm volatile("ldmatrix.sync.aligned.m8n8.x4.shared.b16 {%0,%1,%2,%3}, [%4];" \
                 : "=r"(r0), "=r"(r1), "=r"(r2), "=r"(r3) : "r"(addr))

// D = A*B + D, m16n8k16, f16 in, f32 acc
#define MMA_16816(c0, c1, c2, c3, a0, a1, a2, a3, b0, b1) \
    asm volatile("mma.sync.aligned.m16n8k16.row.col.f32.f16.f16.f32 " \
                 "{%0,%1,%2,%3}, {%4,%5,%6,%7}, {%8,%9}, {%0,%1,%2,%3};" \
                 : "+f"(c0), "+f"(c1), "+f"(c2), "+f"(c3) \
                 : "r"(a0), "r"(a1), "r"(a2), "r"(a3), "r"(b0), "r"(b1))

// SW128 swizzle of a byte offset within a [row][128B] tile
#define SW128(off) ((off) ^ (((off) >> 3) & 0x70))

// ---------------------------------------------------------------------------
// Fused prologue: x f32->fp16 AND weight dequant, one kernel (2 launches/call
// total so the fixed ncu -s 5 -c 1 window lands on the GEMM).
// ---------------------------------------------------------------------------
static __device__ __forceinline__ uint2 dequant4(unsigned v) {
    // fp16 patterns for field-1: 0 -> -1 (0xBC00), 1 -> 0, 2 -> 1 (0x3C00), 3 -> 2 (0x4000)
    const unsigned long long LUT = 0x40003C000000BC00ull;
    unsigned h0 = (unsigned)((LUT >> (16u * (v & 3u))) & 0xFFFFu);
    unsigned h1 = (unsigned)((LUT >> (16u * ((v >> 2) & 3u))) & 0xFFFFu);
    unsigned h2 = (unsigned)((LUT >> (16u * ((v >> 4) & 3u))) & 0xFFFFu);
    unsigned h3 = (unsigned)((LUT >> (16u * ((v >> 6) & 3u))) & 0xFFFFu);
    return make_uint2(h0 | (h1 << 16), h2 | (h3 << 16));
}

__global__ void __launch_bounds__(256) prep_kernel(
    const float4* __restrict__ x, const int4* __restrict__ pw)
{
    int b = blockIdx.x;
    if (b < CONV_BLOCKS) {
        int i = b * 256 + threadIdx.x;
        float4 v = x[i];
        __half2* A2 = reinterpret_cast<__half2*>(g_A);
        A2[2 * i]     = __floats2half2_rn(v.x, v.y);
        A2[2 * i + 1] = __floats2half2_rn(v.z, v.w);
    } else {
        int i = (b - CONV_BLOCKS) * 256 + threadIdx.x;
        int4 p = pw[i];
        uint2* B2 = reinterpret_cast<uint2*>(g_B);  // 4 halves per uint2
        B2[4 * i + 0] = dequant4((unsigned)p.x);
        B2[4 * i + 1] = dequant4((unsigned)p.y);
        B2[4 * i + 2] = dequant4((unsigned)p.z);
        B2[4 * i + 3] = dequant4((unsigned)p.w);
    }
}

// ---------------------------------------------------------------------------
// Stage loader: 128x64 fp16 A tile + 128x64 fp16 B tile, SW128-swizzled rows
// ---------------------------------------------------------------------------
static __device__ __forceinline__ void load_stage(
    int s, int tid, uint32_t smem_base,
    const __half* __restrict__ Abase, const __half* __restrict__ Bbase)
{
    uint32_t aB = smem_base + (uint32_t)(s % 3) * STAGE_BYTES;
    uint32_t bB = aB + A_TILE_BYTES;
    const __half* As = Abase + (size_t)s * BK;
    const __half* Bs = Bbase + (size_t)s * BK;
    #pragma unroll
    for (int c = 0; c < 4; c++) {
        int chunk = tid + c * NTHREADS;   // 0..1023
        int row = chunk >> 3;             // 0..127
        int col = chunk & 7;              // 16B chunk within 128B row
        uint32_t sw = SW128((uint32_t)(row * 128 + col * 16));
        CP_ASYNC16(aB + sw, As + (size_t)row * K_TOTAL + col * 8);
        CP_ASYNC16(bB + sw, Bs + (size_t)row * K_TOTAL + col * 8);
    }
    CP_COMMIT();
}

// ---------------------------------------------------------------------------
// Main GEMM: 128x128 CTA tile, 8 warps (2 M x 4 N), warp tile 64x32,
// 3-stage cp.async pipeline, ks-pipelined fragments, mma.sync.m16n8k16
// Grid: x = M tiles (fast) so a concurrent wave spans all M for few N columns
// -> B streams from DRAM once.
// ---------------------------------------------------------------------------
__global__ void __launch_bounds__(NTHREADS, 2)
gemm_kernel(const float* __restrict__ scale_p, float* __restrict__ out)
{
    extern __shared__ char smem[];
    uint32_t smem_base = smem_u32(smem);
    int tid = threadIdx.x;
    int wid = tid >> 5;
    int lid = tid & 31;

    int mBase = blockIdx.x * BM;   // M fast
    int nBase = blockIdx.y * BN;

    int warp_m = (wid & 1) * 64;   // 0 or 64 within CTA tile
    int warp_n = (wid >> 1) * 32;  // 0,32,64,96

    const __half* Abase = g_A + (size_t)mBase * K_TOTAL;
    const __half* Bbase = g_B + (size_t)nBase * K_TOTAL;

    // Per-lane ldmatrix addressing (identical scheme for A and B, both [row][K]
    // with 128B swizzled rows):
    int mat  = lid >> 3;
    int r    = lid & 7;
    int rowA0 = warp_m + ((mat & 1) << 3) + r;   // + mi*16
    int rowB0 = warp_n + ((mat & 1) << 3) + r;   // + nb*16
    uint32_t cxor = (uint32_t)(((mat >> 1) << 4)) ^ ((uint32_t)r << 4);

    float acc[4][4][4];   // [mi][ni][4]
    #pragma unroll
    for (int mi = 0; mi < 4; mi++)
        #pragma unroll
        for (int ni = 0; ni < 4; ni++)
            #pragma unroll
            for (int c = 0; c < 4; c++) acc[mi][ni][c] = 0.0f;

    uint32_t a_frag[2][4][4];   // [buf][mi][4]
    uint32_t b_frag[2][4][2];   // [buf][ni][2]

    load_stage(0, tid, smem_base, Abase, Bbase);
    load_stage(1, tid, smem_base, Abase, Bbase);

    for (int s = 0; s < S_STAGES; s++) {
        if (s + 1 < S_STAGES) { CP_WAIT1(); } else { CP_WAIT0(); }
        __syncthreads();

        if (s + 2 < S_STAGES) load_stage(s + 2, tid, smem_base, Abase, Bbase);

        uint32_t aT = smem_base + (uint32_t)(s % 3) * STAGE_BYTES;
        uint32_t bT = aT + A_TILE_BYTES;

        // Load ks=0 fragments into buffer 0
        {
            uint32_t kb = cxor;   // ks = 0
            #pragma unroll
            for (int mi = 0; mi < 4; mi++) {
                uint32_t addr = aT + (uint32_t)((rowA0 + mi * 16) * 128) + kb;
                LDMATRIX_X4(a_frag[0][mi][0], a_frag[0][mi][1],
                            a_frag[0][mi][2], a_frag[0][mi][3], addr);
            }
            #pragma unroll
            for (int nb = 0; nb < 2; nb++) {
                uint32_t r0, r1, r2, r3;
                uint32_t addr = bT + (uint32_t)((rowB0 + nb * 16) * 128) + kb;
                LDMATRIX_X4(r0, r1, r2, r3, addr);
                b_frag[0][nb * 2 + 0][0] = r0; b_frag[0][nb * 2 + 0][1] = r2;
                b_frag[0][nb * 2 + 1][0] = r1; b_frag[0][nb * 2 + 1][1] = r3;
            }
        }

        #pragma unroll
        for (int ks = 0; ks < 4; ks++) {
            int cur = ks & 1;
            int nxt = cur ^ 1;
            if (ks < 3) {
                // Prefetch ks+1 fragments while ks's MMAs execute
                uint32_t kb = (uint32_t)((ks + 1) * 32) ^ cxor;
                #pragma unroll
                for (int mi = 0; mi < 4; mi++) {
                    uint32_t addr = aT + (uint32_t)((rowA0 + mi * 16) * 128) + kb;
                    LDMATRIX_X4(a_frag[nxt][mi][0], a_frag[nxt][mi][1],
                                a_frag[nxt][mi][2], a_frag[nxt][mi][3], addr);
                }
                #pragma unroll
                for (int nb = 0; nb < 2; nb++) {
                    uint32_t r0, r1, r2, r3;
                    uint32_t addr = bT + (uint32_t)((rowB0 + nb * 16) * 128) + kb;
                    LDMATRIX_X4(r0, r1, r2, r3, addr);
                    b_frag[nxt][nb * 2 + 0][0] = r0; b_frag[nxt][nb * 2 + 0][1] = r2;
                    b_frag[nxt][nb * 2 + 1][0] = r1; b_frag[nxt][nb * 2 + 1][1] = r3;
                }
            }
            #pragma unroll
            for (int mi = 0; mi < 4; mi++)
                #pragma unroll
                for (int ni = 0; ni < 4; ni++)
                    MMA_16816(acc[mi][ni][0], acc[mi][ni][1],
                              acc[mi][ni][2], acc[mi][ni][3],
                              a_frag[cur][mi][0], a_frag[cur][mi][1],
                              a_frag[cur][mi][2], a_frag[cur][mi][3],
                              b_frag[cur][ni][0], b_frag[cur][ni][1]);
        }
    }

    // Epilogue: c frag m16n8 f32 layout: lane l -> row = l/4 (+8), col = (l%4)*2
    float scale = *scale_p;
    int erow = lid >> 2;
    int ecol = (lid & 3) * 2;

    #pragma unroll
    for (int mi = 0; mi < 4; mi++) {
        #pragma unroll
        for (int ni = 0; ni < 4; ni++) {
            int row = mBase + warp_m + mi * 16 + erow;
            int col = nBase + warp_n + ni * 8 + ecol;
            float2 v0 = make_float2(acc[mi][ni][0] * scale, acc[mi][ni][1] * scale);
            float2 v1 = make_float2(acc[mi][ni][2] * scale, acc[mi][ni][3] * scale);
            *reinterpret_cast<float2*>(out + (size_t)row * N_TOTAL + col) = v0;
            *reinterpret_cast<float2*>(out + (size_t)(row + 8) * N_TOTAL + col) = v1;
        }
    }
}

// ---------------------------------------------------------------------------
// Harness entry
// ---------------------------------------------------------------------------
extern "C" void kernel_launch(void* const* d_in, const int* in_sizes, int n_in,
                              void* d_out, int out_size)
{
    const float* x  = (const float*)d_in[0];
    const int*   pw = (const int*)d_in[1];
    const float* ws = (const float*)d_in[2];
    float* out = (float*)d_out;

    cudaFuncSetAttribute(gemm_kernel,
                         cudaFuncAttributeMaxDynamicSharedMemorySize,
                         SMEM_TOTAL_BYTES);

    prep_kernel<<<PREP_BLOCKS, 256>>>(
        reinterpret_cast<const float4*>(x),
        reinterpret_cast<const int4*>(pw));
    gemm_kernel<<<dim3(M_TOTAL / BM, N_TOTAL / BN), NTHREADS, SMEM_TOTAL_BYTES>>>(ws, out);
}

// round 4
// speedup vs baseline: 1.0596x; 1.0531x over previous
#include <cuda_runtime.h>
#include <cuda_fp16.h>
#include <cstdint>

// ---------------------------------------------------------------------------
// Problem constants
// ---------------------------------------------------------------------------
#define M_TOTAL 4096            // 4 * 1024
#define N_TOTAL 11008
#define K_TOTAL 4096
#define PACKED_LEN (N_TOTAL * K_TOTAL / 4)   // int32 elements, one byte each

#define BM 128
#define BN 256
#define BK 64                   // fp16 elems per stage = 128 bytes = SW128 atom row
#define S_STAGES (K_TOTAL / BK) // 64
#define NTHREADS 256
#define NSTAGES 4

// SMEM: 4 stage buffers, each A tile 16KB + B tile 32KB
#define A_TILE_BYTES 16384
#define B_TILE_BYTES 32768
#define STAGE_BYTES  (A_TILE_BYTES + B_TILE_BYTES)         // 49152
#define SMEM_TOTAL_BYTES (NSTAGES * STAGE_BYTES)           // 196608

// Prep kernel grid split
#define CONV_BLOCKS ((M_TOTAL * K_TOTAL / 4) / 256)    // 16384
#define DEQ_BLOCKS  ((PACKED_LEN / 4) / 256)           // 11008
#define PREP_BLOCKS (CONV_BLOCKS + DEQ_BLOCKS)

// ---------------------------------------------------------------------------
// Device scratch (module-static; no runtime allocation)
// ---------------------------------------------------------------------------
__device__ __half g_A[(size_t)M_TOTAL * K_TOTAL];   // 32 MB, x in fp16
__device__ __half g_B[(size_t)N_TOTAL * K_TOTAL];   // 88 MB, dequantized W

// ---------------------------------------------------------------------------
// PTX helpers (baseline ISA only: cp.async sm_80, ldmatrix sm_75, mma sm_80)
// ---------------------------------------------------------------------------
static __device__ __forceinline__ uint32_t smem_u32(const void* p) {
    uint32_t a;
    asm("{ .reg .u64 t; cvta.to.shared.u64 t, %1; cvt.u32.u64 %0, t; }"
        : "=r"(a) : "l"(p));
    return a;
}

#define CP_ASYNC16(dst, src) \
    asm volatile("cp.async.cg.shared.global [%0], [%1], 16;" \
                 :: "r"(dst), "l"(__cvta_generic_to_global(src)) : "memory")
#define CP_COMMIT() asm volatile("cp.async.commit_group;" ::: "memory")
#define CP_WAIT2()  asm volatile("cp.async.wait_group 2;" ::: "memory")
#define CP_WAIT1()  asm volatile("cp.async.wait_group 1;" ::: "memory")
#define CP_WAIT0()  asm volatile("cp.async.wait_group 0;" ::: "memory")

#define LDMATRIX_X4(r0, r1, r2, r3, addr) \
    asm volatile("ldmatrix.sync.aligned.m8n8.x4.shared.b16 {%0,%1,%2,%3}, [%4];" \
                 : "=r"(r0), "=r"(r1), "=r"(r2), "=r"(r3) : "r"(addr))

// D = A*B + D, m16n8k16, f16 in, f32 acc
#define MMA_16816(c0, c1, c2, c3, a0, a1, a2, a3, b0, b1) \
    asm volatile("mma.sync.aligned.m16n8k16.row.col.f32.f16.f16.f32 " \
                 "{%0,%1,%2,%3}, {%4,%5,%6,%7}, {%8,%9}, {%0,%1,%2,%3};" \
                 : "+f"(c0), "+f"(c1), "+f"(c2), "+f"(c3) \
                 : "r"(a0), "r"(a1), "r"(a2), "r"(a3), "r"(b0), "r"(b1))

// SW128 swizzle of a byte offset within a [row][128B] tile
#define SW128(off) ((off) ^ (((off) >> 3) & 0x70))

// ---------------------------------------------------------------------------
// Fused prologue: x f32->fp16 AND weight dequant (2 launches/call total so
// ncu -s 5 -c 1 lands on gemm_kernel).
// ---------------------------------------------------------------------------
static __device__ __forceinline__ uint2 dequant4(unsigned v) {
    // fp16 patterns for field-1: 0 -> -1 (0xBC00), 1 -> 0, 2 -> 1 (0x3C00), 3 -> 2 (0x4000)
    const unsigned long long LUT = 0x40003C000000BC00ull;
    unsigned h0 = (unsigned)((LUT >> (16u * (v & 3u))) & 0xFFFFu);
    unsigned h1 = (unsigned)((LUT >> (16u * ((v >> 2) & 3u))) & 0xFFFFu);
    unsigned h2 = (unsigned)((LUT >> (16u * ((v >> 4) & 3u))) & 0xFFFFu);
    unsigned h3 = (unsigned)((LUT >> (16u * ((v >> 6) & 3u))) & 0xFFFFu);
    return make_uint2(h0 | (h1 << 16), h2 | (h3 << 16));
}

__global__ void __launch_bounds__(256) prep_kernel(
    const float4* __restrict__ x, const int4* __restrict__ pw)
{
    int b = blockIdx.x;
    if (b < CONV_BLOCKS) {
        int i = b * 256 + threadIdx.x;
        float4 v = x[i];
        __half2* A2 = reinterpret_cast<__half2*>(g_A);
        A2[2 * i]     = __floats2half2_rn(v.x, v.y);
        A2[2 * i + 1] = __floats2half2_rn(v.z, v.w);
    } else {
        int i = (b - CONV_BLOCKS) * 256 + threadIdx.x;
        int4 p = pw[i];
        uint2* B2 = reinterpret_cast<uint2*>(g_B);  // 4 halves per uint2
        B2[4 * i + 0] = dequant4((unsigned)p.x);
        B2[4 * i + 1] = dequant4((unsigned)p.y);
        B2[4 * i + 2] = dequant4((unsigned)p.z);
        B2[4 * i + 3] = dequant4((unsigned)p.w);
    }
}

// ---------------------------------------------------------------------------
// Stage loader: 128x64 fp16 A tile + 256x64 fp16 B tile, SW128-swizzled rows
// ---------------------------------------------------------------------------
static __device__ __forceinline__ void load_stage(
    int s, int tid, uint32_t smem_base,
    const __half* __restrict__ Abase, const __half* __restrict__ Bbase)
{
    uint32_t aB = smem_base + (uint32_t)(s & 3) * STAGE_BYTES;
    uint32_t bB = aB + A_TILE_BYTES;
    const __half* As = Abase + (size_t)s * BK;
    const __half* Bs = Bbase + (size_t)s * BK;
    #pragma unroll
    for (int c = 0; c < 4; c++) {            // A: 1024 16B chunks
        int chunk = tid + c * NTHREADS;
        int row = chunk >> 3;
        int col = chunk & 7;
        uint32_t sw = SW128((uint32_t)(row * 128 + col * 16));
        CP_ASYNC16(aB + sw, As + (size_t)row * K_TOTAL + col * 8);
    }
    #pragma unroll
    for (int c = 0; c < 8; c++) {            // B: 2048 16B chunks
        int chunk = tid + c * NTHREADS;
        int row = chunk >> 3;
        int col = chunk & 7;
        uint32_t sw = SW128((uint32_t)(row * 128 + col * 16));
        CP_ASYNC16(bB + sw, Bs + (size_t)row * K_TOTAL + col * 8);
    }
    CP_COMMIT();
}

// ---------------------------------------------------------------------------
// Main GEMM: 128x256 CTA tile, 8 warps (2 M x 4 N), warp tile 64x64,
// 4-stage cp.async pipeline with cross-stage fragment prefetch.
// Grid: x = M tiles (fast) so a wave spans all M for few N columns.
// ---------------------------------------------------------------------------
__global__ void __launch_bounds__(NTHREADS, 1)
gemm_kernel(const float* __restrict__ scale_p, float* __restrict__ out)
{
    extern __shared__ char smem[];
    uint32_t smem_base = smem_u32(smem);
    int tid = threadIdx.x;
    int wid = tid >> 5;
    int lid = tid & 31;

    int mBase = blockIdx.x * BM;   // M fast
    int nBase = blockIdx.y * BN;

    int warp_m = (wid & 1) * 64;   // 0 or 64
    int warp_n = (wid >> 1) * 64;  // 0,64,128,192

    const __half* Abase = g_A + (size_t)mBase * K_TOTAL;
    const __half* Bbase = g_B + (size_t)nBase * K_TOTAL;

    // ldmatrix per-lane addressing (A and B identical: [row][K], 128B swizzled rows)
    int mat  = lid >> 3;
    int r    = lid & 7;
    int rowA0 = warp_m + ((mat & 1) << 3) + r;   // + mi*16
    int rowB0 = warp_n + ((mat & 1) << 3) + r;   // + nb*16
    uint32_t cxor = (uint32_t)(((mat >> 1) << 4)) ^ ((uint32_t)r << 4);

    float acc[4][8][4];   // [mi][ni][4]
    #pragma unroll
    for (int mi = 0; mi < 4; mi++)
        #pragma unroll
        for (int ni = 0; ni < 8; ni++)
            #pragma unroll
            for (int c = 0; c < 4; c++) acc[mi][ni][c] = 0.0f;

    uint32_t a_frag[2][4][4];   // [buf][mi][4]
    uint32_t b_frag[2][8][2];   // [buf][ni][2]

    load_stage(0, tid, smem_base, Abase, Bbase);
    load_stage(1, tid, smem_base, Abase, Bbase);
    load_stage(2, tid, smem_base, Abase, Bbase);
    CP_WAIT2();                  // stage 0 resident
    __syncthreads();

    // Preload stage 0, ks 0 fragments into buffer 0
    {
        uint32_t aT = smem_base;
        uint32_t bT = aT + A_TILE_BYTES;
        #pragma unroll
        for (int mi = 0; mi < 4; mi++) {
            uint32_t addr = aT + (uint32_t)((rowA0 + mi * 16) * 128) + cxor;
            LDMATRIX_X4(a_frag[0][mi][0], a_frag[0][mi][1],
                        a_frag[0][mi][2], a_frag[0][mi][3], addr);
        }
        #pragma unroll
        for (int nb = 0; nb < 4; nb++) {
            uint32_t r0, r1, r2, r3;
            uint32_t addr = bT + (uint32_t)((rowB0 + nb * 16) * 128) + cxor;
            LDMATRIX_X4(r0, r1, r2, r3, addr);
            b_frag[0][nb * 2 + 0][0] = r0; b_frag[0][nb * 2 + 0][1] = r2;
            b_frag[0][nb * 2 + 1][0] = r1; b_frag[0][nb * 2 + 1][1] = r3;
        }
    }

    for (int s = 0; s < S_STAGES; s++) {
        // Guarantee stages <= s+1 resident (s+1 needed for cross-stage prefetch)
        if (s + 2 < S_STAGES) { CP_WAIT1(); } else { CP_WAIT0(); }
        __syncthreads();

        if (s + 3 < S_STAGES) load_stage(s + 3, tid, smem_base, Abase, Bbase);

        uint32_t aT = smem_base + (uint32_t)(s & 3) * STAGE_BYTES;
        uint32_t bT = aT + A_TILE_BYTES;

        #pragma unroll
        for (int ks = 0; ks < 4; ks++) {
            int cur = ks & 1;
            int nxt = cur ^ 1;

            // Prefetch next fragment set: ks+1 of this stage, or ks=0 of stage s+1
            if (ks < 3) {
                uint32_t kb = (uint32_t)((ks + 1) * 32) ^ cxor;
                #pragma unroll
                for (int mi = 0; mi < 4; mi++) {
                    uint32_t addr = aT + (uint32_t)((rowA0 + mi * 16) * 128) + kb;
                    LDMATRIX_X4(a_frag[nxt][mi][0], a_frag[nxt][mi][1],
                                a_frag[nxt][mi][2], a_frag[nxt][mi][3], addr);
                }
                #pragma unroll
                for (int nb = 0; nb < 4; nb++) {
                    uint32_t r0, r1, r2, r3;
                    uint32_t addr = bT + (uint32_t)((rowB0 + nb * 16) * 128) + kb;
                    LDMATRIX_X4(r0, r1, r2, r3, addr);
                    b_frag[nxt][nb * 2 + 0][0] = r0; b_frag[nxt][nb * 2 + 0][1] = r2;
                    b_frag[nxt][nb * 2 + 1][0] = r1; b_frag[nxt][nb * 2 + 1][1] = r3;
                }
            } else if (s + 1 < S_STAGES) {
                uint32_t aT2 = smem_base + (uint32_t)((s + 1) & 3) * STAGE_BYTES;
                uint32_t bT2 = aT2 + A_TILE_BYTES;
                #pragma unroll
                for (int mi = 0; mi < 4; mi++) {
                    uint32_t addr = aT2 + (uint32_t)((rowA0 + mi * 16) * 128) + cxor;
                    LDMATRIX_X4(a_frag[nxt][mi][0], a_frag[nxt][mi][1],
                                a_frag[nxt][mi][2], a_frag[nxt][mi][3], addr);
                }
                #pragma unroll
                for (int nb = 0; nb < 4; nb++) {
                    uint32_t r0, r1, r2, r3;
                    uint32_t addr = bT2 + (uint32_t)((rowB0 + nb * 16) * 128) + cxor;
                    LDMATRIX_X4(r0, r1, r2, r3, addr);
                    b_frag[nxt][nb * 2 + 0][0] = r0; b_frag[nxt][nb * 2 + 0][1] = r2;
                    b_frag[nxt][nb * 2 + 1][0] = r1; b_frag[nxt][nb * 2 + 1][1] = r3;
                }
            }

            #pragma unroll
            for (int mi = 0; mi < 4; mi++)
                #pragma unroll
                for (int ni = 0; ni < 8; ni++)
                    MMA_16816(acc[mi][ni][0], acc[mi][ni][1],
                              acc[mi][ni][2], acc[mi][ni][3],
                              a_frag[cur][mi][0], a_frag[cur][mi][1],
                              a_frag[cur][mi][2], a_frag[cur][mi][3],
                              b_frag[cur][ni][0], b_frag[cur][ni][1]);
        }
    }

    // Epilogue: c frag m16n8 f32 layout: lane l -> row = l/4 (+8), col = (l%4)*2
    float scale = *scale_p;
    int erow = lid >> 2;
    int ecol = (lid & 3) * 2;

    #pragma unroll
    for (int mi = 0; mi < 4; mi++) {
        #pragma unroll
        for (int ni = 0; ni < 8; ni++) {
            int row = mBase + warp_m + mi * 16 + erow;
            int col = nBase + warp_n + ni * 8 + ecol;
            float2 v0 = make_float2(acc[mi][ni][0] * scale, acc[mi][ni][1] * scale);
            float2 v1 = make_float2(acc[mi][ni][2] * scale, acc[mi][ni][3] * scale);
            *reinterpret_cast<float2*>(out + (size_t)row * N_TOTAL + col) = v0;
            *reinterpret_cast<float2*>(out + (size_t)(row + 8) * N_TOTAL + col) = v1;
        }
    }
}

// ---------------------------------------------------------------------------
// Harness entry
// ---------------------------------------------------------------------------
extern "C" void kernel_launch(void* const* d_in, const int* in_sizes, int n_in,
                              void* d_out, int out_size)
{
    const float* x  = (const float*)d_in[0];
    const int*   pw = (const int*)d_in[1];
    const float* ws = (const float*)d_in[2];
    float* out = (float*)d_out;

    cudaFuncSetAttribute(gemm_kernel,
                         cudaFuncAttributeMaxDynamicSharedMemorySize,
                         SMEM_TOTAL_BYTES);

    prep_kernel<<<PREP_BLOCKS, 256>>>(
        reinterpret_cast<const float4*>(x),
        reinterpret_cast<const int4*>(pw));
    gemm_kernel<<<dim3(M_TOTAL / BM, N_TOTAL / BN), NTHREADS, SMEM_TOTAL_BYTES>>>(ws, out);
}

// round 5
// speedup vs baseline: 1.0823x; 1.0214x over previous
#include <cuda_runtime.h>
#include <cuda_fp16.h>
#include <cstdint>

// ---------------------------------------------------------------------------
// Problem constants
// ---------------------------------------------------------------------------
#define M_TOTAL 4096            // 4 * 1024
#define N_TOTAL 11008
#define K_TOTAL 4096
#define PACKED_LEN (N_TOTAL * K_TOTAL / 4)   // int32 elements, one byte each

#define BM 128
#define BN 256
#define BK 64                   // fp16 elems per stage = 128 bytes = SW128 atom row
#define S_STAGES (K_TOTAL / BK) // 64
#define NTHREADS 256
#define NSTAGES 4

// SMEM: 4 stage buffers, each A tile 16KB + B tile 32KB
#define A_TILE_BYTES 16384
#define B_TILE_BYTES 32768
#define STAGE_BYTES  (A_TILE_BYTES + B_TILE_BYTES)         // 49152
#define SMEM_TOTAL_BYTES (NSTAGES * STAGE_BYTES)           // 196608

// Prep kernel grid split
#define CONV_BLOCKS ((M_TOTAL * K_TOTAL / 4) / 256)    // 16384
#define DEQ_BLOCKS  ((PACKED_LEN / 4) / 256)           // 11008
#define PREP_BLOCKS (CONV_BLOCKS + DEQ_BLOCKS)

// ---------------------------------------------------------------------------
// Device scratch (module-static; no runtime allocation)
// ---------------------------------------------------------------------------
__device__ __half g_A[(size_t)M_TOTAL * K_TOTAL];   // 32 MB, x in fp16
__device__ __half g_B[(size_t)N_TOTAL * K_TOTAL];   // 88 MB, dequantized W

// ---------------------------------------------------------------------------
// PTX helpers (baseline ISA only: cp.async sm_80, ldmatrix sm_75, mma sm_80)
// ---------------------------------------------------------------------------
static __device__ __forceinline__ uint32_t smem_u32(const void* p) {
    uint32_t a;
    asm("{ .reg .u64 t; cvta.to.shared.u64 t, %1; cvt.u32.u64 %0, t; }"
        : "=r"(a) : "l"(p));
    return a;
}

#define CP_ASYNC16(dst, src) \
    asm volatile("cp.async.cg.shared.global [%0], [%1], 16;" \
                 :: "r"(dst), "l"(src) : "memory")
#define CP_COMMIT() asm volatile("cp.async.commit_group;" ::: "memory")
#define CP_WAIT2()  asm volatile("cp.async.wait_group 2;" ::: "memory")
#define CP_WAIT1()  asm volatile("cp.async.wait_group 1;" ::: "memory")
#define CP_WAIT0()  asm volatile("cp.async.wait_group 0;" ::: "memory")

#define LDMATRIX_X4(r0, r1, r2, r3, addr) \
    asm volatile("ldmatrix.sync.aligned.m8n8.x4.shared.b16 {%0,%1,%2,%3}, [%4];" \
                 : "=r"(r0), "=r"(r1), "=r"(r2), "=r"(r3) : "r"(addr))

// D = A*B + D, m16n8k16, f16 in, f32 acc
#define MMA_16816(c0, c1, c2, c3, a0, a1, a2, a3, b0, b1) \
    asm volatile("mma.sync.aligned.m16n8k16.row.col.f32.f16.f16.f32 " \
                 "{%0,%1,%2,%3}, {%4,%5,%6,%7}, {%8,%9}, {%0,%1,%2,%3};" \
                 : "+f"(c0), "+f"(c1), "+f"(c2), "+f"(c3) \
                 : "r"(a0), "r"(a1), "r"(a2), "r"(a3), "r"(b0), "r"(b1))

// SW128 swizzle of a byte offset within a [row][128B] tile
#define SW128(off) ((off) ^ (((off) >> 3) & 0x70))

// ---------------------------------------------------------------------------
// Fused prologue: x f32->fp16 AND weight dequant (2 launches/call total so
// ncu -s 5 -c 1 lands on gemm_kernel).
// ---------------------------------------------------------------------------
static __device__ __forceinline__ uint2 dequant4(unsigned v) {
    // fp16 patterns for field-1: 0 -> -1 (0xBC00), 1 -> 0, 2 -> 1 (0x3C00), 3 -> 2 (0x4000)
    const unsigned long long LUT = 0x40003C000000BC00ull;
    unsigned h0 = (unsigned)((LUT >> (16u * (v & 3u))) & 0xFFFFu);
    unsigned h1 = (unsigned)((LUT >> (16u * ((v >> 2) & 3u))) & 0xFFFFu);
    unsigned h2 = (unsigned)((LUT >> (16u * ((v >> 4) & 3u))) & 0xFFFFu);
    unsigned h3 = (unsigned)((LUT >> (16u * ((v >> 6) & 3u))) & 0xFFFFu);
    return make_uint2(h0 | (h1 << 16), h2 | (h3 << 16));
}

__global__ void __launch_bounds__(256) prep_kernel(
    const float4* __restrict__ x, const int4* __restrict__ pw)
{
    int b = blockIdx.x;
    if (b < CONV_BLOCKS) {
        int i = b * 256 + threadIdx.x;
        float4 v = x[i];
        __half2* A2 = reinterpret_cast<__half2*>(g_A);
        A2[2 * i]     = __floats2half2_rn(v.x, v.y);
        A2[2 * i + 1] = __floats2half2_rn(v.z, v.w);
    } else {
        int i = (b - CONV_BLOCKS) * 256 + threadIdx.x;
        int4 p = pw[i];
        uint2* B2 = reinterpret_cast<uint2*>(g_B);  // 4 halves per uint2
        B2[4 * i + 0] = dequant4((unsigned)p.x);
        B2[4 * i + 1] = dequant4((unsigned)p.y);
        B2[4 * i + 2] = dequant4((unsigned)p.z);
        B2[4 * i + 3] = dequant4((unsigned)p.w);
    }
}

// ---------------------------------------------------------------------------
// Stage loader with hoisted addressing:
//   gA/gB: per-thread base byte pointers for stage 0 chunk 0
//   swA/swB: per-thread swizzled smem offsets for chunk 0 (stage-invariant)
//   Chunk c adds compile-time constants: +32c rows -> +32c*K*2 bytes gmem,
//   +4096c bytes smem (swizzle bits unaffected since row%8 unchanged).
// ---------------------------------------------------------------------------
static __device__ __forceinline__ void load_stage(
    int s, uint32_t smem_base, uint32_t swA, uint32_t swB,
    const char* gA, const char* gB)
{
    uint32_t aB = smem_base + (uint32_t)(s & 3) * STAGE_BYTES + swA;
    uint32_t bB = smem_base + (uint32_t)(s & 3) * STAGE_BYTES + A_TILE_BYTES + swB;
    const char* As = gA + (size_t)s * (BK * 2);
    const char* Bs = gB + (size_t)s * (BK * 2);
    #pragma unroll
    for (int c = 0; c < 4; c++)              // A: rows tid>>3 + 32c
        CP_ASYNC16(aB + 4096u * c, As + (size_t)c * 32 * K_TOTAL * 2);
    #pragma unroll
    for (int c = 0; c < 8; c++)              // B: rows tid>>3 + 32c
        CP_ASYNC16(bB + 4096u * c, Bs + (size_t)c * 32 * K_TOTAL * 2);
    CP_COMMIT();
}

// ---------------------------------------------------------------------------
// Main GEMM: 128x256 CTA tile, 8 warps (2 M x 4 N), warp tile 64x64,
// 4-stage cp.async pipeline, cross-stage fragment prefetch, LDSM interleaved
// with MMA groups. Grid: x = M tiles (fast) -> B streams from DRAM once.
// ---------------------------------------------------------------------------
__global__ void __launch_bounds__(NTHREADS, 1)
gemm_kernel(const float* __restrict__ scale_p, float* __restrict__ out)
{
    extern __shared__ char smem[];
    uint32_t smem_base = smem_u32(smem);
    int tid = threadIdx.x;
    int wid = tid >> 5;
    int lid = tid & 31;

    int mBase = blockIdx.x * BM;   // M fast
    int nBase = blockIdx.y * BN;

    int warp_m = (wid & 1) * 64;   // 0 or 64
    int warp_n = (wid >> 1) * 64;  // 0,64,128,192

    // ---- hoisted cp.async addressing (per-thread, once) ----
    int ldRow = tid >> 3;          // 0..31
    int ldCol = tid & 7;           // 16B chunk in row
    uint32_t swBase = SW128((uint32_t)(ldRow * 128 + ldCol * 16));
    const char* gA = reinterpret_cast<const char*>(
        g_A + (size_t)(mBase + ldRow) * K_TOTAL + ldCol * 8);
    const char* gB = reinterpret_cast<const char*>(
        g_B + (size_t)(nBase + ldRow) * K_TOTAL + ldCol * 8);

    // ---- hoisted ldmatrix addressing ----
    int mat  = lid >> 3;
    int r    = lid & 7;
    int rowA0 = warp_m + ((mat & 1) << 3) + r;
    int rowB0 = warp_n + ((mat & 1) << 3) + r;
    uint32_t cxor = (uint32_t)(((mat >> 1) << 4)) ^ ((uint32_t)r << 4);
    uint32_t arA[4], arB[4];
    #pragma unroll
    for (int mi = 0; mi < 4; mi++) arA[mi] = (uint32_t)((rowA0 + mi * 16) * 128);
    #pragma unroll
    for (int nb = 0; nb < 4; nb++) arB[nb] = (uint32_t)((rowB0 + nb * 16) * 128)
                                             + A_TILE_BYTES;

    float acc[4][8][4];
    #pragma unroll
    for (int mi = 0; mi < 4; mi++)
        #pragma unroll
        for (int ni = 0; ni < 8; ni++)
            #pragma unroll
            for (int c = 0; c < 4; c++) acc[mi][ni][c] = 0.0f;

    uint32_t a_frag[2][4][4];
    uint32_t b_frag[2][8][2];

    load_stage(0, smem_base, swBase, swBase, gA, gB);
    load_stage(1, smem_base, swBase, swBase, gA, gB);
    load_stage(2, smem_base, swBase, swBase, gA, gB);
    CP_WAIT2();
    __syncthreads();

    // Preload stage 0, ks 0 fragments into buffer 0
    {
        #pragma unroll
        for (int mi = 0; mi < 4; mi++)
            LDMATRIX_X4(a_frag[0][mi][0], a_frag[0][mi][1],
                        a_frag[0][mi][2], a_frag[0][mi][3],
                        smem_base + arA[mi] + cxor);
        #pragma unroll
        for (int nb = 0; nb < 4; nb++) {
            uint32_t r0, r1, r2, r3;
            LDMATRIX_X4(r0, r1, r2, r3, smem_base + arB[nb] + cxor);
            b_frag[0][nb * 2 + 0][0] = r0; b_frag[0][nb * 2 + 0][1] = r2;
            b_frag[0][nb * 2 + 1][0] = r1; b_frag[0][nb * 2 + 1][1] = r3;
        }
    }

    for (int s = 0; s < S_STAGES; s++) {
        // Stages <= s+1 resident (s+1 needed for cross-stage prefetch)
        if (s + 2 < S_STAGES) { CP_WAIT1(); } else { CP_WAIT0(); }
        __syncthreads();

        if (s + 3 < S_STAGES) load_stage(s + 3, smem_base, swBase, swBase, gA, gB);

        uint32_t stageT = smem_base + (uint32_t)(s & 3) * STAGE_BYTES;

        #pragma unroll
        for (int ks = 0; ks < 4; ks++) {
            int cur = ks & 1;
            int nxt = cur ^ 1;

            // Prefetch target: ks+1 of this stage, or ks=0 of stage s+1
            uint32_t pT, pkb;
            bool do_pref;
            if (ks < 3) {
                pT = stageT; pkb = (uint32_t)((ks + 1) * 32) ^ cxor; do_pref = true;
            } else {
                pT = smem_base + (uint32_t)((s + 1) & 3) * STAGE_BYTES;
                pkb = cxor;
                do_pref = (s + 1 < S_STAGES);
            }

            // 8 groups: 1 interleaved LDSM + 4 MMAs each
            #pragma unroll
            for (int g = 0; g < 8; g++) {
                if (do_pref) {
                    if (g < 4) {
                        LDMATRIX_X4(a_frag[nxt][g][0], a_frag[nxt][g][1],
                                    a_frag[nxt][g][2], a_frag[nxt][g][3],
                                    pT + arA[g] + pkb);
                    } else {
                        int nb = g - 4;
                        uint32_t r0, r1, r2, r3;
                        LDMATRIX_X4(r0, r1, r2, r3, pT + arB[nb] + pkb);
                        b_frag[nxt][nb * 2 + 0][0] = r0; b_frag[nxt][nb * 2 + 0][1] = r2;
                        b_frag[nxt][nb * 2 + 1][0] = r1; b_frag[nxt][nb * 2 + 1][1] = r3;
                    }
                }
                int mi = g & 3;
                int nh = (g >> 2) * 4;
                #pragma unroll
                for (int nj = 0; nj < 4; nj++) {
                    int ni = nh + nj;
                    MMA_16816(acc[mi][ni][0], acc[mi][ni][1],
                              acc[mi][ni][2], acc[mi][ni][3],
                              a_frag[cur][mi][0], a_frag[cur][mi][1],
                              a_frag[cur][mi][2], a_frag[cur][mi][3],
                              b_frag[cur][ni][0], b_frag[cur][ni][1]);
                }
            }
        }
    }

    // Epilogue: c frag m16n8 f32 layout: lane l -> row = l/4 (+8), col = (l%4)*2
    float scale = *scale_p;
    int erow = lid >> 2;
    int ecol = (lid & 3) * 2;

    #pragma unroll
    for (int mi = 0; mi < 4; mi++) {
        #pragma unroll
        for (int ni = 0; ni < 8; ni++) {
            int row = mBase + warp_m + mi * 16 + erow;
            int col = nBase + warp_n + ni * 8 + ecol;
            float2 v0 = make_float2(acc[mi][ni][0] * scale, acc[mi][ni][1] * scale);
            float2 v1 = make_float2(acc[mi][ni][2] * scale, acc[mi][ni][3] * scale);
            *reinterpret_cast<float2*>(out + (size_t)row * N_TOTAL + col) = v0;
            *reinterpret_cast<float2*>(out + (size_t)(row + 8) * N_TOTAL + col) = v1;
        }
    }
}

// ---------------------------------------------------------------------------
// Harness entry
// ---------------------------------------------------------------------------
extern "C" void kernel_launch(void* const* d_in, const int* in_sizes, int n_in,
                              void* d_out, int out_size)
{
    const float* x  = (const float*)d_in[0];
    const int*   pw = (const int*)d_in[1];
    const float* ws = (const float*)d_in[2];
    float* out = (float*)d_out;

    cudaFuncSetAttribute(gemm_kernel,
                         cudaFuncAttributeMaxDynamicSharedMemorySize,
                         SMEM_TOTAL_BYTES);

    prep_kernel<<<PREP_BLOCKS, 256>>>(
        reinterpret_cast<const float4*>(x),
        reinterpret_cast<const int4*>(pw));
    gemm_kernel<<<dim3(M_TOTAL / BM, N_TOTAL / BN), NTHREADS, SMEM_TOTAL_BYTES>>>(ws, out);
}